// round 3
// baseline (speedup 1.0000x reference)
#include <cuda_runtime.h>
#include <cstddef>

// Problem dims (fixed): (B=2, C=1, D=160, H=192, W=160) fp32, WIN=9 box, zero pad
#define Bn 2
#define Dn 160
#define Hn 192
#define Wn 160
#define Rr 4
#define HW (Hn*Wn)
#define DHW (Dn*HW)
#define NB (Bn*DHW)          // 9,830,400

#define TH 32
#define TW 32
#define SH (TH + 2*Rr)       // 40
#define SW (TW + 2*Rr)       // 40
#define SWP 41               // padded stride for sI/sJ (conflict-free W-sum reads)
#define TMPS 33              // padded col stride for tmp
#define TMPCH (SH*TMPS)      // 1320 floats per channel
#define RINGCH (TH*TW + 4)   // 1028 floats per channel (pad keeps 16B align + bank shift)
#define RINGSLOT (5*RINGCH)  // 5140

#define DSPLIT 2
#define DCHUNK (Dn/DSPLIT)   // 80
#define NHT (Hn/TH)          // 6
#define NWT (Wn/TW)          // 5
#define NTILES (Bn*NHT*NWT*DSPLIT)  // 120

#define NT 256

// dynamic smem layout (floats): sI[40*41] sJ[40*41] tmp[5*1320] ring[9*5140]
#define OFF_SJ   (SH*SWP)                   // 1640
#define OFF_TMP  (2*SH*SWP)                 // 3280
#define OFF_RING (OFF_TMP + 5*TMPCH)        // 9880
#define SMEM_FLOATS (OFF_RING + 9*RINGSLOT) // 56140
#define SMEM_BYTES (SMEM_FLOATS*4)          // 224,560

__device__ double g_part[NTILES];
__device__ unsigned int g_done = 0;

__global__ void __launch_bounds__(NT, 1)
ncc_fused(const float* __restrict__ I, const float* __restrict__ J,
          float* __restrict__ out) {
    extern __shared__ float smem[];
    float* sI   = smem;
    float* sJ   = smem + OFF_SJ;
    float* tmp  = smem + OFF_TMP;
    float* ring = smem + OFF_RING;

    const int tid = threadIdx.x;
    const int tile = blockIdx.x;

    // decode tile: [b][ht][wt][chunk]
    int t = tile;
    const int chunk = t % DSPLIT;  t /= DSPLIT;
    const int wt    = t % NWT;     t /= NWT;
    const int ht    = t % NHT;
    const int b     = t / NHT;

    const int h0 = ht * TH;
    const int w0 = wt * TW;
    const int o0 = chunk * DCHUNK;
    const int o1 = o0 + DCHUNK;
    const int p0   = (o0 - Rr > 0) ? (o0 - Rr) : 0;
    const int dEnd = o1 - 1 + Rr;       // may exceed Dn-1: tail outputs need
                                        // zero planes beyond the volume.

    // register D-window sums: 5 channels x 4 pixels (pixels tid*4 .. tid*4+3)
    float S0x=0,S0y=0,S0z=0,S0w=0;
    float S1x=0,S1y=0,S1z=0,S1w=0;
    float S2x=0,S2y=0,S2z=0,S2w=0;
    float S3x=0,S3y=0,S3z=0,S3w=0;
    float S4x=0,S4y=0,S4z=0,S4w=0;
    float accf = 0.f;

    const float inv = 1.0f / 729.0f;
    const size_t bbase = (size_t)b * DHW;

    for (int dp = p0; dp <= dEnd; ++dp) {
        const bool valid = (dp < Dn);   // uniform across the block

        if (valid) {
            // ---- stage: load input plane tile (with halo, zero-padded) ----
            const size_t pbase = bbase + (size_t)dp * HW;
            for (int idx = tid; idx < SH * SW; idx += NT) {
                const int r = idx / SW;
                const int c = idx - r * SW;
                const int gh = h0 - Rr + r;
                const int gw = w0 - Rr + c;
                float a = 0.f, q = 0.f;
                if ((unsigned)gh < (unsigned)Hn && (unsigned)gw < (unsigned)Wn) {
                    const size_t g = pbase + (size_t)gh * Wn + gw;
                    a = I[g];
                    q = J[g];
                }
                sI[r * SWP + c] = a;
                sJ[r * SWP + c] = q;
            }
            __syncthreads();

            // ---- W-sum: 9-tap along W, 5 channels, into tmp[ch][40][32] ----
            if (tid < 160) {
                const int r  = tid >> 2;
                const int cg = tid & 3;
                const int c0 = cg * 8;
                float iv[16], jv[16];
#pragma unroll
                for (int k = 0; k < 16; ++k) {
                    iv[k] = sI[r * SWP + c0 + k];
                    jv[k] = sJ[r * SWP + c0 + k];
                }
                float s0=0,s1=0,s2=0,s3=0,s4=0;
#pragma unroll
                for (int k = 0; k < 9; ++k) {
                    const float a = iv[k], q = jv[k];
                    s0 += a; s1 += q; s2 += a*a; s3 += q*q; s4 += a*q;
                }
                float* tp = tmp + r * TMPS + c0;
#pragma unroll
                for (int j = 0; j < 8; ++j) {
                    tp[0*TMPCH + j] = s0;
                    tp[1*TMPCH + j] = s1;
                    tp[2*TMPCH + j] = s2;
                    tp[3*TMPCH + j] = s3;
                    tp[4*TMPCH + j] = s4;
                    if (j < 7) {
                        const float an = iv[j+9], qn = jv[j+9];
                        const float ao = iv[j],   qo = jv[j];
                        s0 += an - ao;
                        s1 += qn - qo;
                        s2 += an*an - ao*ao;
                        s3 += qn*qn - qo*qo;
                        s4 += an*qn - ao*qo;
                    }
                }
            }
            __syncthreads();

            // ---- H-sum: 9-tap along H, rolling register window -> ring ----
            const int slot = dp % 9;
            if (tid < 160) {
                const int ch  = tid >> 5;
                const int col = tid & 31;
                const float* tc = tmp + ch * TMPCH + col;
                float win[9];
                float s = 0.f;
#pragma unroll
                for (int k = 0; k < 9; ++k) {
                    const float v = tc[k * TMPS];
                    win[k] = v;
                    s += v;
                }
                float* rp = ring + slot * RINGSLOT + ch * RINGCH + col;
#pragma unroll
                for (int tt = 0; tt < 32; ++tt) {
                    rp[tt * TW] = s;
                    if (tt < 31) {
                        const float nv = tc[(tt + 9) * TMPS];
                        s += nv - win[tt % 9];
                        win[tt % 9] = nv;
                    }
                }
            }
            __syncthreads();

            // ---- add new plane into register D-window ----
            const float* np = ring + slot * RINGSLOT;
            float4 v;
            v = *(const float4*)(np + 0*RINGCH + 4*tid); S0x+=v.x; S0y+=v.y; S0z+=v.z; S0w+=v.w;
            v = *(const float4*)(np + 1*RINGCH + 4*tid); S1x+=v.x; S1y+=v.y; S1z+=v.z; S1w+=v.w;
            v = *(const float4*)(np + 2*RINGCH + 4*tid); S2x+=v.x; S2y+=v.y; S2z+=v.z; S2w+=v.w;
            v = *(const float4*)(np + 3*RINGCH + 4*tid); S3x+=v.x; S3y+=v.y; S3z+=v.z; S3w+=v.w;
            v = *(const float4*)(np + 4*RINGCH + 4*tid); S4x+=v.x; S4y+=v.y; S4z+=v.z; S4w+=v.w;
        }
        // (dp >= Dn: plane is implicit zero — nothing to add)

        // ---- cc epilogue at output o = dp - Rr (window [o-4,o+4] clipped) ----
        {
            const int o = dp - Rr;
            if (o >= o0 && o < o1) {
                {
                    const float mu1 = S0x*inv, mu2 = S1x*inv;
                    const float v1 = S2x*inv - mu1*mu1;
                    const float v2 = S3x*inv - mu2*mu2;
                    const float cv = S4x*inv - mu1*mu2;
                    accf += __fdividef(cv*cv, v1*v2 + 1e-5f);
                }
                {
                    const float mu1 = S0y*inv, mu2 = S1y*inv;
                    const float v1 = S2y*inv - mu1*mu1;
                    const float v2 = S3y*inv - mu2*mu2;
                    const float cv = S4y*inv - mu1*mu2;
                    accf += __fdividef(cv*cv, v1*v2 + 1e-5f);
                }
                {
                    const float mu1 = S0z*inv, mu2 = S1z*inv;
                    const float v1 = S2z*inv - mu1*mu1;
                    const float v2 = S3z*inv - mu2*mu2;
                    const float cv = S4z*inv - mu1*mu2;
                    accf += __fdividef(cv*cv, v1*v2 + 1e-5f);
                }
                {
                    const float mu1 = S0w*inv, mu2 = S1w*inv;
                    const float v1 = S2w*inv - mu1*mu1;
                    const float v2 = S3w*inv - mu2*mu2;
                    const float cv = S4w*inv - mu1*mu2;
                    accf += __fdividef(cv*cv, v1*v2 + 1e-5f);
                }
            }

            // ---- drop plane leaving the window ----
            const int q = dp - 2*Rr;
            if (q >= p0) {                    // q < Dn always (q <= dEnd-8)
                const float* op = ring + (q % 9) * RINGSLOT;
                float4 v;
                v = *(const float4*)(op + 0*RINGCH + 4*tid); S0x-=v.x; S0y-=v.y; S0z-=v.z; S0w-=v.w;
                v = *(const float4*)(op + 1*RINGCH + 4*tid); S1x-=v.x; S1y-=v.y; S1z-=v.z; S1w-=v.w;
                v = *(const float4*)(op + 2*RINGCH + 4*tid); S2x-=v.x; S2y-=v.y; S2z-=v.z; S2w-=v.w;
                v = *(const float4*)(op + 3*RINGCH + 4*tid); S3x-=v.x; S3y-=v.y; S3z-=v.z; S3w-=v.w;
                v = *(const float4*)(op + 4*RINGCH + 4*tid); S4x-=v.x; S4y-=v.y; S4z-=v.z; S4w-=v.w;
            }
        }
        __syncthreads();   // ring slot reuse + sI reuse across iterations
    }

    // ---- block reduction (deterministic) ----
    double* red = (double*)smem;
    red[tid] = (double)accf;
    __syncthreads();
#pragma unroll
    for (int s = 128; s > 0; s >>= 1) {
        if (tid < s) red[tid] += red[tid + s];
        __syncthreads();
    }

    __shared__ int isLast;
    if (tid == 0) {
        g_part[tile] = red[0];
        __threadfence();
        const unsigned v = atomicAdd(&g_done, 1u);
        isLast = (v == (unsigned)(gridDim.x - 1));
    }
    __syncthreads();

    // ---- last block: deterministic fixed-order final sum ----
    if (isLast) {
        __threadfence();
        double a = (tid < NTILES) ? g_part[tid] : 0.0;
        red[tid] = a;
        __syncthreads();
#pragma unroll
        for (int s = 128; s > 0; s >>= 1) {
            if (tid < s) red[tid] += red[tid + s];
            __syncthreads();
        }
        if (tid == 0) {
            out[0] = (float)(-red[0] / (double)NB);
            g_done = 0;   // reset for next graph replay
        }
    }
}

extern "C" void kernel_launch(void* const* d_in, const int* in_sizes, int n_in,
                              void* d_out, int out_size) {
    const float* I = (const float*)d_in[0];   // y_true
    const float* J = (const float*)d_in[1];   // y_pred
    float* out = (float*)d_out;

    static int configured = 0;
    if (!configured) {
        cudaFuncSetAttribute(ncc_fused,
                             cudaFuncAttributeMaxDynamicSharedMemorySize,
                             SMEM_BYTES);
        configured = 1;
    }

    ncc_fused<<<NTILES, NT, SMEM_BYTES>>>(I, J, out);
}

// round 4
// speedup vs baseline: 1.2759x; 1.2759x over previous
#include <cuda_runtime.h>
#include <cstddef>

// Problem dims (fixed): (B=2, C=1, D=160, H=192, W=160) fp32, WIN=9 box, zero pad
#define Bn 2
#define Dn 160
#define Hn 192
#define Wn 160
#define Rr 4
#define HW (Hn*Wn)
#define DHW (Dn*HW)
#define NB (Bn*DHW)          // 9,830,400
#define NCH 5

#define HSPLIT 4
#define HCHUNK (Hn/HSPLIT)   // 48

#define DSPLIT 4
#define DCHUNK (Dn/DSPLIT)   // 40
#define NPART (Bn*Hn*DSPLIT) // 1536

// Scratch: WH-filtered 5 channels
__device__ float g_buf[NCH * NB];    // ~196.6 MB
__device__ double g_part[NPART];
__device__ unsigned int g_done = 0;

// ---------------------------------------------------------------------------
// K1: fused W+H 9-tap box sums for 5 stat channels (I, J, I*I, J*J, I*J).
// One block per (b, d, h-chunk); 160 threads = one per w. Streams rows:
//   - stage row (I,J) into double-buffered smem row (halo zero-padded)
//   - 9-tap W-sum from smem into registers, add to rolling H-sums
//   - wsum history kept in a per-thread-column smem ring (9 slots, no sync:
//     each thread only ever touches its own w column -> conflict-free)
//   - emit output row o = r-4, then subtract wsum(o-4) from rolling sums
// One __syncthreads per row (staging buffer reuse only).
// ---------------------------------------------------------------------------
__global__ void __launch_bounds__(Wn)
pass_wh(const float* __restrict__ I, const float* __restrict__ J,
        float* __restrict__ out) {
    __shared__ float sbufI[2][Wn + 2*Rr];
    __shared__ float sbufJ[2][Wn + 2*Rr];
    __shared__ float ring[NCH][9][Wn];

    const int blk = blockIdx.x;
    const int hs  = blk % HSPLIT;
    const int rem = blk / HSPLIT;
    const int d   = rem % Dn;
    const int b   = rem / Dn;
    const int w   = threadIdx.x;

    const size_t pbase = (size_t)b * DHW + (size_t)d * HW;
    const int h0 = hs * HCHUNK;

    float s0=0.f, s1=0.f, s2=0.f, s3=0.f, s4=0.f;
    int slot = 0;  // = (r - (h0-4)) % 9

    for (int r = h0 - Rr; r <= h0 + HCHUNK + Rr - 1; ++r) {
        const int buf = r & 1;
        const bool rv = (r >= 0) && (r < Hn);

        if (rv) {
            const float a = I[pbase + (size_t)r * Wn + w];
            const float q = J[pbase + (size_t)r * Wn + w];
            sbufI[buf][w + Rr] = a;
            sbufJ[buf][w + Rr] = q;
            if (w < Rr)       { sbufI[buf][w] = 0.f;          sbufJ[buf][w] = 0.f; }
            if (w >= Wn - Rr) { sbufI[buf][w + 2*Rr] = 0.f;   sbufJ[buf][w + 2*Rr] = 0.f; }
        }
        __syncthreads();

        float w0=0.f, w1=0.f, w2=0.f, w3=0.f, w4=0.f;
        if (rv) {
#pragma unroll
            for (int k = 0; k < 9; ++k) {
                const float a = sbufI[buf][w + k];
                const float q = sbufJ[buf][w + k];
                w0 += a; w1 += q; w2 += a*a; w3 += q*q; w4 += a*q;
            }
        }
        s0 += w0; s1 += w1; s2 += w2; s3 += w3; s4 += w4;

        // store wsum history in per-thread column of the ring (zeros for
        // invalid rows keep later subtracts consistent)
        ring[0][slot][w] = w0;
        ring[1][slot][w] = w1;
        ring[2][slot][w] = w2;
        ring[3][slot][w] = w3;
        ring[4][slot][w] = w4;

        const int o = r - Rr;
        if (o >= h0) {                       // o < h0+HCHUNK always holds here
            const size_t gi = pbase + (size_t)o * Wn + w;
            out[0*(size_t)NB + gi] = s0;
            out[1*(size_t)NB + gi] = s1;
            out[2*(size_t)NB + gi] = s2;
            out[3*(size_t)NB + gi] = s3;
            out[4*(size_t)NB + gi] = s4;

            // subtract wsum(o-4), staged 8 iterations ago -> slot (slot+1)%9
            const int q = r - 2*Rr;
            if (q >= 0) {
                const int ssub = (slot + 1 == 9) ? 0 : slot + 1;
                s0 -= ring[0][ssub][w];
                s1 -= ring[1][ssub][w];
                s2 -= ring[2][ssub][w];
                s3 -= ring[3][ssub][w];
                s4 -= ring[4][ssub][w];
            }
        }
        slot = (slot + 1 == 9) ? 0 : slot + 1;
    }
}

// ---------------------------------------------------------------------------
// K2: 9-tap sliding-window sum along D for 5 channels + cc epilogue + mean.
// One block per (b, h, d-chunk); 160 threads = one per w (fully coalesced).
// Final reduction folded into the last-arriving block (deterministic order).
// ---------------------------------------------------------------------------
__global__ void __launch_bounds__(Wn)
pass_d_cc(const float* __restrict__ in, float* __restrict__ outscalar) {
    const int blk   = blockIdx.x;
    const int chunk = blk % DSPLIT;
    const int id    = blk / DSPLIT;
    const int h     = id % Hn;
    const int b     = id / Hn;
    const int w     = threadIdx.x;

    const float* __restrict__ p = in + (size_t)b * DHW + (size_t)h * Wn + w;

    const int o0 = chunk * DCHUNK;
    const int o1 = o0 + DCHUNK;

    float s0=0.f, s1=0.f, s2=0.f, s3=0.f, s4=0.f;
#pragma unroll
    for (int d = o0 - Rr; d <= o0 + Rr; ++d) {
        if (d >= 0 && d < Dn) {
            const size_t off = (size_t)d * HW;
            s0 += p[0*(size_t)NB + off];
            s1 += p[1*(size_t)NB + off];
            s2 += p[2*(size_t)NB + off];
            s3 += p[3*(size_t)NB + off];
            s4 += p[4*(size_t)NB + off];
        }
    }

    const float inv = 1.0f / 729.0f;
    float accf = 0.f;
    for (int o = o0; o < o1; ++o) {
        const float mu1 = s0 * inv;
        const float mu2 = s1 * inv;
        const float v1  = s2 * inv - mu1 * mu1;
        const float v2  = s3 * inv - mu2 * mu2;
        const float cv  = s4 * inv - mu1 * mu2;
        accf += __fdividef(cv * cv, v1 * v2 + 1e-5f);

        const int da = o + Rr + 1;
        const int ds = o - Rr;
        if (da < Dn) {
            const size_t off = (size_t)da * HW;
            s0 += p[0*(size_t)NB + off];
            s1 += p[1*(size_t)NB + off];
            s2 += p[2*(size_t)NB + off];
            s3 += p[3*(size_t)NB + off];
            s4 += p[4*(size_t)NB + off];
        }
        if (ds >= 0) {
            const size_t off = (size_t)ds * HW;
            s0 -= p[0*(size_t)NB + off];
            s1 -= p[1*(size_t)NB + off];
            s2 -= p[2*(size_t)NB + off];
            s3 -= p[3*(size_t)NB + off];
            s4 -= p[4*(size_t)NB + off];
        }
    }

    // Deterministic block reduction (160 -> 1)
    __shared__ double red[Wn];
    red[w] = (double)accf;
    __syncthreads();
    if (w < 32) red[w] += red[w + 128];      // fold 160 -> 128
    __syncthreads();
#pragma unroll
    for (int s = 64; s > 0; s >>= 1) {
        if (w < s) red[w] += red[w + s];
        __syncthreads();
    }

    __shared__ int isLast;
    if (w == 0) {
        g_part[blk] = red[0];
        __threadfence();
        const unsigned v = atomicAdd(&g_done, 1u);
        isLast = (v == (unsigned)(gridDim.x - 1));
    }
    __syncthreads();

    if (isLast) {
        __threadfence();
        double a = 0.0;
        for (int i = w; i < NPART; i += Wn) a += g_part[i];  // fixed order
        red[w] = a;
        __syncthreads();
        if (w < 32) red[w] += red[w + 128];
        __syncthreads();
#pragma unroll
        for (int s = 64; s > 0; s >>= 1) {
            if (w < s) red[w] += red[w + s];
            __syncthreads();
        }
        if (w == 0) {
            outscalar[0] = (float)(-red[0] / (double)NB);
            g_done = 0;   // reset for next graph replay
        }
    }
}

extern "C" void kernel_launch(void* const* d_in, const int* in_sizes, int n_in,
                              void* d_out, int out_size) {
    const float* I = (const float*)d_in[0];   // y_true
    const float* J = (const float*)d_in[1];   // y_pred
    float* out = (float*)d_out;

    float* buf;
    cudaGetSymbolAddress((void**)&buf, g_buf);

    pass_wh<<<Bn * Dn * HSPLIT, Wn>>>(I, J, buf);
    pass_d_cc<<<NPART, Wn>>>(buf, out);
}

// round 5
// speedup vs baseline: 1.4210x; 1.1137x over previous
#include <cuda_runtime.h>
#include <cstddef>

// Problem dims (fixed): (B=2, C=1, D=160, H=192, W=160) fp32, WIN=9 box, zero pad
#define Bn 2
#define Dn 160
#define Hn 192
#define Wn 160
#define Rr 4
#define HW (Hn*Wn)
#define DHW (Dn*HW)
#define NB (Bn*DHW)          // 9,830,400
#define NCH 5
#define NQ (Wn/4)            // 40 w-quads

// K1 decomposition
#define HSPLIT 4
#define HCHUNK (Hn/HSPLIT)   // 48
#define HSUB (HCHUNK/4)      // 12 output rows per thread

// K2 decomposition
#define DSPLIT2 5
#define DCHUNK2 (Dn/DSPLIT2)           // 32
#define NPART2 (Bn*(Hn/4)*DSPLIT2)     // 480

__device__ float g_buf[NCH * NB];      // WH-filtered 5 channels (~196.6 MB)
__device__ double g_part[NPART2];
__device__ unsigned int g_done = 0;

// ---------------------------------------------------------------------------
// helpers
// ---------------------------------------------------------------------------
__device__ __forceinline__ float4 f4zero() { return make_float4(0.f,0.f,0.f,0.f); }

// Given 12 consecutive values v[0..11] (global w = 4*wq-4+k), produce the four
// 9-tap sums: out.{x,y,z,w} = sum v[p..p+8], p=0..3 (sliding).
__device__ __forceinline__ float4 slide9(const float v[12]) {
    float s = v[0]+v[1]+v[2]+v[3]+v[4]+v[5]+v[6]+v[7]+v[8];
    float4 o;
    o.x = s; s += v[9]  - v[0]; 
    o.y = s; s += v[10] - v[1];
    o.z = s; s += v[11] - v[2];
    o.w = s;
    return o;
}

// Load one row's 12-value neighborhood for a w-quad (zero-padded at W edges)
// and produce the 5 channel W-sums.
__device__ __forceinline__ void row_wsums(const float* __restrict__ rI,
                                          const float* __restrict__ rJ,
                                          int wq,
                                          float4& w0, float4& w1, float4& w2,
                                          float4& w3, float4& w4) {
    const float4 aL = (wq > 0)      ? *(const float4*)(rI - 4) : f4zero();
    const float4 aC =                 *(const float4*)(rI);
    const float4 aR = (wq < NQ - 1) ? *(const float4*)(rI + 4) : f4zero();
    const float4 bL = (wq > 0)      ? *(const float4*)(rJ - 4) : f4zero();
    const float4 bC =                 *(const float4*)(rJ);
    const float4 bR = (wq < NQ - 1) ? *(const float4*)(rJ + 4) : f4zero();

    float x[12] = {aL.x,aL.y,aL.z,aL.w, aC.x,aC.y,aC.z,aC.w, aR.x,aR.y,aR.z,aR.w};
    float y[12] = {bL.x,bL.y,bL.z,bL.w, bC.x,bC.y,bC.z,bC.w, bR.x,bR.y,bR.z,bR.w};

    w0 = slide9(x);
    w1 = slide9(y);
    float t[12];
#pragma unroll
    for (int k = 0; k < 12; ++k) t[k] = x[k]*x[k];
    w2 = slide9(t);
#pragma unroll
    for (int k = 0; k < 12; ++k) t[k] = y[k]*y[k];
    w3 = slide9(t);
#pragma unroll
    for (int k = 0; k < 12; ++k) t[k] = x[k]*y[k];
    w4 = slide9(t);
}

#define ADD4(S,V) do{ S.x+=V.x; S.y+=V.y; S.z+=V.z; S.w+=V.w; }while(0)
#define SUB4(S,V) do{ S.x-=V.x; S.y-=V.y; S.z-=V.z; S.w-=V.w; }while(0)

// ---------------------------------------------------------------------------
// K1: fused W+H 9-tap box sums, no smem, no syncs. Thread = one w-quad and
// one 12-row H substream; rolling H window subtracts by recomputing the
// leaving row from global (L1-resident, loaded 8 iterations earlier).
// Grid: Bn*Dn*HSPLIT, block 160 (40 quads x 4 substreams).
// ---------------------------------------------------------------------------
__global__ void __launch_bounds__(160)
pass_wh(const float* __restrict__ I, const float* __restrict__ J,
        float* __restrict__ out) {
    const int blk = blockIdx.x;
    const int hs  = blk % HSPLIT;
    const int rem = blk / HSPLIT;
    const int d   = rem % Dn;
    const int b   = rem / Dn;

    const int tid  = threadIdx.x;
    const int wq   = tid % NQ;
    const int hsub = tid / NQ;                 // 0..3
    const int hbeg = hs * HCHUNK + hsub * HSUB;

    const size_t pbase = (size_t)b * DHW + (size_t)d * HW;
    const float* baseI = I + pbase + 4*wq;
    const float* baseJ = J + pbase + 4*wq;
    float* baseO = out + pbase + 4*wq;

    float4 S0=f4zero(), S1=f4zero(), S2=f4zero(), S3=f4zero(), S4=f4zero();

    for (int r = hbeg - Rr; r <= hbeg + HSUB + Rr - 1; ++r) {
        if ((unsigned)r < (unsigned)Hn) {
            float4 w0,w1,w2,w3,w4;
            row_wsums(baseI + (size_t)r*Wn, baseJ + (size_t)r*Wn, wq,
                      w0,w1,w2,w3,w4);
            ADD4(S0,w0); ADD4(S1,w1); ADD4(S2,w2); ADD4(S3,w3); ADD4(S4,w4);
        }
        const int o = r - Rr;
        if (o >= hbeg) {
            float* op = baseO + (size_t)o * Wn;
            *(float4*)(op + 0*(size_t)NB) = S0;
            *(float4*)(op + 1*(size_t)NB) = S1;
            *(float4*)(op + 2*(size_t)NB) = S2;
            *(float4*)(op + 3*(size_t)NB) = S3;
            *(float4*)(op + 4*(size_t)NB) = S4;

            const int qr = r - 2*Rr;           // row leaving the window
            if (qr >= 0) {
                float4 w0,w1,w2,w3,w4;
                row_wsums(baseI + (size_t)qr*Wn, baseJ + (size_t)qr*Wn, wq,
                          w0,w1,w2,w3,w4);
                SUB4(S0,w0); SUB4(S1,w1); SUB4(S2,w2); SUB4(S3,w3); SUB4(S4,w4);
            }
        }
    }
}

// ---------------------------------------------------------------------------
// K2: 9-tap sliding sum along D (float4 per thread) + cc + global mean.
// Grid: Bn*(Hn/4)*DSPLIT2, block 160 (40 quads x 4 h rows).
// ---------------------------------------------------------------------------
__global__ void __launch_bounds__(160)
pass_d_cc(const float* __restrict__ in, float* __restrict__ outscalar) {
    const int blk   = blockIdx.x;
    const int chunk = blk % DSPLIT2;
    const int id    = blk / DSPLIT2;
    const int hg    = id % (Hn/4);
    const int b     = id / (Hn/4);

    const int tid = threadIdx.x;
    const int wq  = tid % NQ;
    const int h   = hg * 4 + tid / NQ;

    const float* __restrict__ p =
        in + (size_t)b * DHW + (size_t)h * Wn + 4*wq;

    const int o0 = chunk * DCHUNK2;
    const int o1 = o0 + DCHUNK2;

    float4 S0=f4zero(), S1=f4zero(), S2=f4zero(), S3=f4zero(), S4=f4zero();
#pragma unroll
    for (int d = o0 - Rr; d <= o0 + Rr; ++d) {
        if (d >= 0 && d < Dn) {
            const size_t off = (size_t)d * HW;
            float4 v;
            v = *(const float4*)(p + 0*(size_t)NB + off); ADD4(S0,v);
            v = *(const float4*)(p + 1*(size_t)NB + off); ADD4(S1,v);
            v = *(const float4*)(p + 2*(size_t)NB + off); ADD4(S2,v);
            v = *(const float4*)(p + 3*(size_t)NB + off); ADD4(S3,v);
            v = *(const float4*)(p + 4*(size_t)NB + off); ADD4(S4,v);
        }
    }

    const float inv = 1.0f / 729.0f;
    float accf = 0.f;
    for (int o = o0; o < o1; ++o) {
        {
            const float mu1=S0.x*inv, mu2=S1.x*inv;
            const float v1=S2.x*inv-mu1*mu1, v2=S3.x*inv-mu2*mu2, cv=S4.x*inv-mu1*mu2;
            accf += __fdividef(cv*cv, v1*v2 + 1e-5f);
        }
        {
            const float mu1=S0.y*inv, mu2=S1.y*inv;
            const float v1=S2.y*inv-mu1*mu1, v2=S3.y*inv-mu2*mu2, cv=S4.y*inv-mu1*mu2;
            accf += __fdividef(cv*cv, v1*v2 + 1e-5f);
        }
        {
            const float mu1=S0.z*inv, mu2=S1.z*inv;
            const float v1=S2.z*inv-mu1*mu1, v2=S3.z*inv-mu2*mu2, cv=S4.z*inv-mu1*mu2;
            accf += __fdividef(cv*cv, v1*v2 + 1e-5f);
        }
        {
            const float mu1=S0.w*inv, mu2=S1.w*inv;
            const float v1=S2.w*inv-mu1*mu1, v2=S3.w*inv-mu2*mu2, cv=S4.w*inv-mu1*mu2;
            accf += __fdividef(cv*cv, v1*v2 + 1e-5f);
        }

        const int da = o + Rr + 1;
        const int ds = o - Rr;
        if (da < Dn) {
            const size_t off = (size_t)da * HW;
            float4 v;
            v = *(const float4*)(p + 0*(size_t)NB + off); ADD4(S0,v);
            v = *(const float4*)(p + 1*(size_t)NB + off); ADD4(S1,v);
            v = *(const float4*)(p + 2*(size_t)NB + off); ADD4(S2,v);
            v = *(const float4*)(p + 3*(size_t)NB + off); ADD4(S3,v);
            v = *(const float4*)(p + 4*(size_t)NB + off); ADD4(S4,v);
        }
        if (ds >= 0) {
            const size_t off = (size_t)ds * HW;
            float4 v;
            v = *(const float4*)(p + 0*(size_t)NB + off); SUB4(S0,v);
            v = *(const float4*)(p + 1*(size_t)NB + off); SUB4(S1,v);
            v = *(const float4*)(p + 2*(size_t)NB + off); SUB4(S2,v);
            v = *(const float4*)(p + 3*(size_t)NB + off); SUB4(S3,v);
            v = *(const float4*)(p + 4*(size_t)NB + off); SUB4(S4,v);
        }
    }

    // Deterministic block reduction (160 -> 1)
    __shared__ double red[160];
    const int w = tid;
    red[w] = (double)accf;
    __syncthreads();
    if (w < 32) red[w] += red[w + 128];
    __syncthreads();
#pragma unroll
    for (int s = 64; s > 0; s >>= 1) {
        if (w < s) red[w] += red[w + s];
        __syncthreads();
    }

    __shared__ int isLast;
    if (w == 0) {
        g_part[blk] = red[0];
        __threadfence();
        const unsigned v = atomicAdd(&g_done, 1u);
        isLast = (v == (unsigned)(gridDim.x - 1));
    }
    __syncthreads();

    if (isLast) {
        __threadfence();
        double a = 0.0;
        for (int i = w; i < NPART2; i += 160) a += g_part[i];  // fixed order
        red[w] = a;
        __syncthreads();
        if (w < 32) red[w] += red[w + 128];
        __syncthreads();
#pragma unroll
        for (int s = 64; s > 0; s >>= 1) {
            if (w < s) red[w] += red[w + s];
            __syncthreads();
        }
        if (w == 0) {
            outscalar[0] = (float)(-red[0] / (double)NB);
            g_done = 0;   // reset for next graph replay
        }
    }
}

extern "C" void kernel_launch(void* const* d_in, const int* in_sizes, int n_in,
                              void* d_out, int out_size) {
    const float* I = (const float*)d_in[0];   // y_true
    const float* J = (const float*)d_in[1];   // y_pred
    float* out = (float*)d_out;

    float* buf;
    cudaGetSymbolAddress((void**)&buf, g_buf);

    pass_wh<<<Bn * Dn * HSPLIT, 160>>>(I, J, buf);
    pass_d_cc<<<Bn * (Hn/4) * DSPLIT2, 160>>>(buf, out);
}

// round 6
// speedup vs baseline: 1.4568x; 1.0252x over previous
#include <cuda_runtime.h>
#include <cstddef>

// Problem dims (fixed): (B=2, C=1, D=160, H=192, W=160) fp32, WIN=9 box, zero pad
#define Bn 2
#define Dn 160
#define Hn 192
#define Wn 160
#define Rr 4
#define HW (Hn*Wn)
#define DHW (Dn*HW)
#define NB (Bn*DHW)          // 9,830,400
#define NCH 5
#define NQ (Wn/4)            // 40 w-quads

// K1 (H-filter) decomposition
#define HSPLIT 4
#define HCHUNK (Hn/HSPLIT)   // 48
#define HSUB (HCHUNK/4)      // 12 output rows per thread

// K2 (D-filter + W-filter + cc) decomposition
#define DSPLIT 10
#define DCHUNK (Dn/DSPLIT)   // 16
#define NROWS 4              // h rows per block
#define NPART (Bn*(Hn/NROWS)*DSPLIT)   // 960

#define SROW 42              // padded quad row in smem: [0]=left pad, [41]=right pad

__device__ float g_buf[NCH * NB];      // H-filtered 5 channels (~196.6 MB)
__device__ double g_part[NPART];
__device__ unsigned int g_done = 0;

__device__ __forceinline__ float4 f4zero() { return make_float4(0.f,0.f,0.f,0.f); }
#define ADD4(S,V) do{ S.x+=V.x; S.y+=V.y; S.z+=V.z; S.w+=V.w; }while(0)
#define SUB4(S,V) do{ S.x-=V.x; S.y-=V.y; S.z-=V.z; S.w-=V.w; }while(0)

// 12 consecutive values -> four 9-tap sliding sums
__device__ __forceinline__ float4 slide9(const float v[12]) {
    float s = v[0]+v[1]+v[2]+v[3]+v[4]+v[5]+v[6]+v[7]+v[8];
    float4 o;
    o.x = s; s += v[9]  - v[0];
    o.y = s; s += v[10] - v[1];
    o.z = s; s += v[11] - v[2];
    o.w = s;
    return o;
}

// ---------------------------------------------------------------------------
// K1: 9-tap H-filter on raw voxels, 5 stat channels. Rolling window along h;
// the subtract side RELOADS the raw row (L1/L2 hit, exact telescoping) and
// recomputes just 3 products — no W-filter here, so no slide9 in the hot loop.
// Thread = one w-quad, one 12-row h substream. No smem, no syncs.
// ---------------------------------------------------------------------------
__global__ void __launch_bounds__(160)
pass_h(const float* __restrict__ I, const float* __restrict__ J,
       float* __restrict__ out) {
    const int blk = blockIdx.x;
    const int hs  = blk % HSPLIT;
    const int rem = blk / HSPLIT;
    const int d   = rem % Dn;
    const int b   = rem / Dn;

    const int tid  = threadIdx.x;
    const int wq   = tid % NQ;
    const int hsub = tid / NQ;                 // 0..3
    const int hbeg = hs * HCHUNK + hsub * HSUB;

    const size_t pbase = (size_t)b * DHW + (size_t)d * HW + 4*wq;
    const float* bI = I + pbase;
    const float* bJ = J + pbase;
    float* bO = out + pbase;

    float4 S0=f4zero(), S1=f4zero(), S2=f4zero(), S3=f4zero(), S4=f4zero();

    for (int r = hbeg - Rr; r <= hbeg + HSUB + Rr - 1; ++r) {
        if ((unsigned)r < (unsigned)Hn) {
            const float4 a = *(const float4*)(bI + (size_t)r * Wn);
            const float4 q = *(const float4*)(bJ + (size_t)r * Wn);
            ADD4(S0,a); ADD4(S1,q);
            S2.x += a.x*a.x; S2.y += a.y*a.y; S2.z += a.z*a.z; S2.w += a.w*a.w;
            S3.x += q.x*q.x; S3.y += q.y*q.y; S3.z += q.z*q.z; S3.w += q.w*q.w;
            S4.x += a.x*q.x; S4.y += a.y*q.y; S4.z += a.z*q.z; S4.w += a.w*q.w;
        }
        const int o = r - Rr;
        if (o >= hbeg) {
            float* op = bO + (size_t)o * Wn;
            *(float4*)(op + 0*(size_t)NB) = S0;
            *(float4*)(op + 1*(size_t)NB) = S1;
            *(float4*)(op + 2*(size_t)NB) = S2;
            *(float4*)(op + 3*(size_t)NB) = S3;
            *(float4*)(op + 4*(size_t)NB) = S4;

            const int qr = o - Rr;             // row leaving the window
            if (qr >= 0) {
                const float4 a = *(const float4*)(bI + (size_t)qr * Wn);
                const float4 q = *(const float4*)(bJ + (size_t)qr * Wn);
                SUB4(S0,a); SUB4(S1,q);
                S2.x -= a.x*a.x; S2.y -= a.y*a.y; S2.z -= a.z*a.z; S2.w -= a.w*a.w;
                S3.x -= q.x*q.x; S3.y -= q.y*q.y; S3.z -= q.z*q.z; S3.w -= q.w*q.w;
                S4.x -= a.x*q.x; S4.y -= a.y*q.y; S4.z -= a.z*q.z; S4.w -= a.w*q.w;
            }
        }
    }
}

// ---------------------------------------------------------------------------
// K2: D-filter (register rolling window, direct add/sub loads) on H-sums,
// then the W 9-tap applied ONCE per output plane via a double-buffered smem
// row stage (one __syncthreads per plane), then cc + global mean.
// Block: 160 threads = 40 quads x 4 h-rows. Grid: Bn*(Hn/4)*DSPLIT.
// ---------------------------------------------------------------------------
__global__ void __launch_bounds__(160)
pass_d_w_cc(const float* __restrict__ in, float* __restrict__ outscalar) {
    __shared__ float4 sbuf[2][NROWS][NCH][SROW];

    const int blk   = blockIdx.x;
    const int chunk = blk % DSPLIT;
    const int id    = blk / DSPLIT;
    const int hg    = id % (Hn/NROWS);
    const int b     = id / (Hn/NROWS);

    const int tid  = threadIdx.x;
    const int wq   = tid % NQ;
    const int row4 = tid / NQ;                 // 0..3
    const int h    = hg * NROWS + row4;

    const float* __restrict__ p =
        in + (size_t)b * DHW + (size_t)h * Wn + 4*wq;

    const int o0 = chunk * DCHUNK;
    const int o1 = o0 + DCHUNK;

    // zero the W pads once (both buffers): 2*4*5*2 = 80 float4s
    for (int i = tid; i < 80; i += 160) {
        const int side = i & 1;
        const int ch   = (i >> 1) % NCH;
        const int rr   = ((i >> 1) / NCH) % NROWS;
        const int bf   = (i >> 1) / (NCH * NROWS);
        sbuf[bf][rr][ch][side ? (SROW-1) : 0] = f4zero();
    }

    // init D window: planes [max(0,o0-4) .. o0+4]
    float4 S0=f4zero(), S1=f4zero(), S2=f4zero(), S3=f4zero(), S4=f4zero();
#pragma unroll
    for (int d = o0 - Rr; d <= o0 + Rr; ++d) {
        if (d >= 0) {
            const size_t off = (size_t)d * HW;
            float4 v;
            v = *(const float4*)(p + 0*(size_t)NB + off); ADD4(S0,v);
            v = *(const float4*)(p + 1*(size_t)NB + off); ADD4(S1,v);
            v = *(const float4*)(p + 2*(size_t)NB + off); ADD4(S2,v);
            v = *(const float4*)(p + 3*(size_t)NB + off); ADD4(S3,v);
            v = *(const float4*)(p + 4*(size_t)NB + off); ADD4(S4,v);
        }
    }

    const float inv = 1.0f / 729.0f;
    float accf = 0.f;

    for (int o = o0; o < o1; ++o) {
        const int buf = o & 1;
        sbuf[buf][row4][0][1+wq] = S0;
        sbuf[buf][row4][1][1+wq] = S1;
        sbuf[buf][row4][2][1+wq] = S2;
        sbuf[buf][row4][3][1+wq] = S3;
        sbuf[buf][row4][4][1+wq] = S4;
        __syncthreads();

        // W 9-tap from smem (pads give zero boundary), then cc
        float4 W[NCH];
#pragma unroll
        for (int ch = 0; ch < NCH; ++ch) {
            const float4 L = sbuf[buf][row4][ch][wq];
            const float4 C = sbuf[buf][row4][ch][1+wq];
            const float4 R = sbuf[buf][row4][ch][2+wq];
            const float v[12] = {L.x,L.y,L.z,L.w, C.x,C.y,C.z,C.w, R.x,R.y,R.z,R.w};
            W[ch] = slide9(v);
        }
        {
            const float mu1=W[0].x*inv, mu2=W[1].x*inv;
            const float v1=W[2].x*inv-mu1*mu1, v2=W[3].x*inv-mu2*mu2, cv=W[4].x*inv-mu1*mu2;
            accf += __fdividef(cv*cv, v1*v2 + 1e-5f);
        }
        {
            const float mu1=W[0].y*inv, mu2=W[1].y*inv;
            const float v1=W[2].y*inv-mu1*mu1, v2=W[3].y*inv-mu2*mu2, cv=W[4].y*inv-mu1*mu2;
            accf += __fdividef(cv*cv, v1*v2 + 1e-5f);
        }
        {
            const float mu1=W[0].z*inv, mu2=W[1].z*inv;
            const float v1=W[2].z*inv-mu1*mu1, v2=W[3].z*inv-mu2*mu2, cv=W[4].z*inv-mu1*mu2;
            accf += __fdividef(cv*cv, v1*v2 + 1e-5f);
        }
        {
            const float mu1=W[0].w*inv, mu2=W[1].w*inv;
            const float v1=W[2].w*inv-mu1*mu1, v2=W[3].w*inv-mu2*mu2, cv=W[4].w*inv-mu1*mu2;
            accf += __fdividef(cv*cv, v1*v2 + 1e-5f);
        }

        // advance D window
        const int da = o + Rr + 1;
        const int ds = o - Rr;
        if (da < Dn) {
            const size_t off = (size_t)da * HW;
            float4 v;
            v = *(const float4*)(p + 0*(size_t)NB + off); ADD4(S0,v);
            v = *(const float4*)(p + 1*(size_t)NB + off); ADD4(S1,v);
            v = *(const float4*)(p + 2*(size_t)NB + off); ADD4(S2,v);
            v = *(const float4*)(p + 3*(size_t)NB + off); ADD4(S3,v);
            v = *(const float4*)(p + 4*(size_t)NB + off); ADD4(S4,v);
        }
        if (ds >= 0) {
            const size_t off = (size_t)ds * HW;
            float4 v;
            v = *(const float4*)(p + 0*(size_t)NB + off); SUB4(S0,v);
            v = *(const float4*)(p + 1*(size_t)NB + off); SUB4(S1,v);
            v = *(const float4*)(p + 2*(size_t)NB + off); SUB4(S2,v);
            v = *(const float4*)(p + 3*(size_t)NB + off); SUB4(S3,v);
            v = *(const float4*)(p + 4*(size_t)NB + off); SUB4(S4,v);
        }
        // double-buffered: no second sync needed
    }

    // Deterministic block reduction (160 -> 1)
    __shared__ double red[160];
    const int w = tid;
    red[w] = (double)accf;
    __syncthreads();
    if (w < 32) red[w] += red[w + 128];
    __syncthreads();
#pragma unroll
    for (int s = 64; s > 0; s >>= 1) {
        if (w < s) red[w] += red[w + s];
        __syncthreads();
    }

    __shared__ int isLast;
    if (w == 0) {
        g_part[blk] = red[0];
        __threadfence();
        const unsigned v = atomicAdd(&g_done, 1u);
        isLast = (v == (unsigned)(gridDim.x - 1));
    }
    __syncthreads();

    if (isLast) {
        __threadfence();
        double a = 0.0;
        for (int i = w; i < NPART; i += 160) a += g_part[i];  // fixed order
        red[w] = a;
        __syncthreads();
        if (w < 32) red[w] += red[w + 128];
        __syncthreads();
#pragma unroll
        for (int s = 64; s > 0; s >>= 1) {
            if (w < s) red[w] += red[w + s];
            __syncthreads();
        }
        if (w == 0) {
            outscalar[0] = (float)(-red[0] / (double)NB);
            g_done = 0;   // reset for next graph replay
        }
    }
}

extern "C" void kernel_launch(void* const* d_in, const int* in_sizes, int n_in,
                              void* d_out, int out_size) {
    const float* I = (const float*)d_in[0];   // y_true
    const float* J = (const float*)d_in[1];   // y_pred
    float* out = (float*)d_out;

    float* buf;
    cudaGetSymbolAddress((void**)&buf, g_buf);

    pass_h<<<Bn * Dn * HSPLIT, 160>>>(I, J, buf);
    pass_d_w_cc<<<Bn * (Hn/NROWS) * DSPLIT, 160>>>(buf, out);
}